// round 9
// baseline (speedup 1.0000x reference)
#include <cuda_runtime.h>
#include <cuda_fp16.h>
#include <math_constants.h>

#define BATCH 1024
#define NGENE 8192
#define NSETS 2048
#define MAX_TOTAL 262144   // >= 2048 * 120

// Scratch (static device globals — no runtime allocation)
__device__ __half g_GT[NGENE * BATCH];    // transposed features, fp16, 16.8 MB
__device__ int2   g_pair[MAX_TOTAL];      // {gene byte offset, weight bits}, 2 MB
__device__ int    g_off[NSETS + 1];       // segment start offsets

// ---------------------------------------------------------------------------
// K1: warp-per-segment softmax. Bounds via binary search on sorted
// segment_ids; publishes g_off and the packed per-edge descriptor
// g_pair[p] = { flat_idx[p] * rowbytes, float_bits(softmax weight) }.
// ---------------------------------------------------------------------------
__global__ void k_softmax(const float* __restrict__ logits,
                          const int* __restrict__ seg,
                          const int* __restrict__ fidx, int total) {
    int warp_id = (blockIdx.x * blockDim.x + threadIdx.x) >> 5;
    if (warp_id >= NSETS) return;
    int lane = threadIdx.x & 31;

    int lo = 0, hi = total;
    while (lo < hi) { int mid = (lo + hi) >> 1; if (seg[mid] < warp_id) lo = mid + 1; else hi = mid; }
    int beg = lo;
    hi = total;
    while (lo < hi) { int mid = (lo + hi) >> 1; if (seg[mid] < warp_id + 1) lo = mid + 1; else hi = mid; }
    int end = lo;

    if (lane == 0) {
        g_off[warp_id] = beg;
        if (warp_id == NSETS - 1) g_off[NSETS] = total;
    }

    float m = -CUDART_INF_F;
    for (int p = beg + lane; p < end; p += 32) m = fmaxf(m, logits[p]);
    #pragma unroll
    for (int o = 16; o; o >>= 1) m = fmaxf(m, __shfl_xor_sync(0xFFFFFFFFu, m, o));

    float sum = 0.0f;
    for (int p = beg + lane; p < end; p += 32) sum += __expf(logits[p] - m);
    #pragma unroll
    for (int o = 16; o; o >>= 1) sum += __shfl_xor_sync(0xFFFFFFFFu, sum, o);

    float inv = (sum > 0.0f) ? (1.0f / sum) : 0.0f;
    for (int p = beg + lane; p < end; p += 32) {
        float w = __expf(logits[p] - m) * inv;
        g_pair[p] = make_int2(fidx[p] * (BATCH * 2), __float_as_int(w));
    }
}

// ---------------------------------------------------------------------------
// K2: tiled transpose + fp16 convert: G(1024 x 8192) f32 -> GT(8192 x 1024) f16
// blockDim (32,8), grid (NGENE/32, BATCH/32)   [round-5 proven form]
// ---------------------------------------------------------------------------
__global__ void k_transpose(const float* __restrict__ G) {
    __shared__ float tile[32][33];
    int gx = blockIdx.x * 32;   // gene base
    int by = blockIdx.y * 32;   // batch base
    int x = gx + threadIdx.x;
    #pragma unroll
    for (int j = 0; j < 32; j += 8)
        tile[threadIdx.y + j][threadIdx.x] = G[(by + threadIdx.y + j) * NGENE + x];
    __syncthreads();
    #pragma unroll
    for (int j = 0; j < 32; j += 8)
        g_GT[(gx + threadIdx.y + j) * BATCH + by + threadIdx.x] =
            __float2half_rn(tile[threadIdx.x][threadIdx.y + j]);
}

// ---------------------------------------------------------------------------
// K3: 2D-tiled aggregation writing out directly.
// grid = (NSETS/8, BATCH/256), block = 256 threads.
// Warp w owns set s0+w over batch rows b0..b0+255; thread = 8 rows (uint4).
// Edge descriptors come via warp-uniform int2 loads (L1-hot, 1 sector).
// Result tile (8 sets x 256 rows) staged in 8KB smem, then written as
// fully-coalesced 32B chunks: out[b0+t][s0..s0+7].
// ---------------------------------------------------------------------------
__device__ __forceinline__ void fma8(float4& a0, float4& a1, uint4 u, float w) {
    float2 v;
    v = __half22float2(*reinterpret_cast<const __half2*>(&u.x));
    a0.x += w * v.x;  a0.y += w * v.y;
    v = __half22float2(*reinterpret_cast<const __half2*>(&u.y));
    a0.z += w * v.x;  a0.w += w * v.y;
    v = __half22float2(*reinterpret_cast<const __half2*>(&u.z));
    a1.x += w * v.x;  a1.y += w * v.y;
    v = __half22float2(*reinterpret_cast<const __half2*>(&u.w));
    a1.z += w * v.x;  a1.w += w * v.y;
}

__global__ __launch_bounds__(256) void k_agg(float* __restrict__ out) {
    int t    = threadIdx.x;
    int warp = t >> 5;
    int lane = t & 31;
    int s0   = blockIdx.x * 8;
    int b0   = blockIdx.y * 256;
    int s    = s0 + warp;

    int beg = g_off[s];
    int n   = g_off[s + 1] - beg;
    if (n > 128) n = 128;             // structural: n <= 120

    const char* gt = reinterpret_cast<const char*>(g_GT) + b0 * 2 + lane * 16;
    const int2* pr = g_pair + beg;

    float4 a0 = make_float4(0.f, 0.f, 0.f, 0.f);
    float4 a1 = make_float4(0.f, 0.f, 0.f, 0.f);

    int i = 0;
    for (; i + 4 <= n; i += 4) {
        int2 p0 = pr[i + 0];
        int2 p1 = pr[i + 1];
        int2 p2 = pr[i + 2];
        int2 p3 = pr[i + 3];
        uint4 u0 = *reinterpret_cast<const uint4*>(gt + p0.x);
        uint4 u1 = *reinterpret_cast<const uint4*>(gt + p1.x);
        uint4 u2 = *reinterpret_cast<const uint4*>(gt + p2.x);
        uint4 u3 = *reinterpret_cast<const uint4*>(gt + p3.x);
        fma8(a0, a1, u0, __int_as_float(p0.y));
        fma8(a0, a1, u1, __int_as_float(p1.y));
        fma8(a0, a1, u2, __int_as_float(p2.y));
        fma8(a0, a1, u3, __int_as_float(p3.y));
    }
    for (; i < n; i++) {
        int2 p = pr[i];
        uint4 u = *reinterpret_cast<const uint4*>(gt + p.x);
        fma8(a0, a1, u, __int_as_float(p.y));
    }

    // Stage tile: buf[set][local batch row]; thread's rows are 8*lane..8*lane+7
    __shared__ float buf[8][256];
    *reinterpret_cast<float4*>(&buf[warp][lane * 8 + 0]) = a0;
    *reinterpret_cast<float4*>(&buf[warp][lane * 8 + 4]) = a1;
    __syncthreads();

    // Coalesced output: thread t writes out[b0+t][s0..s0+7] (32B, sector-full)
    float4 o0, o1;
    o0.x = buf[0][t]; o0.y = buf[1][t]; o0.z = buf[2][t]; o0.w = buf[3][t];
    o1.x = buf[4][t]; o1.y = buf[5][t]; o1.z = buf[6][t]; o1.w = buf[7][t];
    float* dst = out + (size_t)(b0 + t) * NSETS + s0;
    *reinterpret_cast<float4*>(dst)     = o0;
    *reinterpret_cast<float4*>(dst + 4) = o1;
}

// ---------------------------------------------------------------------------
// Launcher (graph-capturable: kernel launches only, default stream ordering)
// ---------------------------------------------------------------------------
extern "C" void kernel_launch(void* const* d_in, const int* in_sizes, int n_in,
                              void* d_out, int out_size) {
    const float* G      = (const float*)d_in[0];
    const float* logits = (const float*)d_in[1];
    const int*   fidx   = (const int*)d_in[2];
    const int*   seg    = (const int*)d_in[3];
    float*       out    = (float*)d_out;
    int total = in_sizes[1];

    k_softmax<<<(NSETS * 32 + 255) / 256, 256>>>(logits, seg, fidx, total);
    k_transpose<<<dim3(NGENE / 32, BATCH / 32), dim3(32, 8)>>>(G);
    k_agg<<<dim3(NSETS / 8, BATCH / 256), 256>>>(out);
}

// round 10
// speedup vs baseline: 1.0843x; 1.0843x over previous
#include <cuda_runtime.h>
#include <cuda_fp16.h>
#include <math_constants.h>

#define BATCH 1024
#define NGENE 8192
#define NSETS 2048
#define MAX_TOTAL 262144   // >= 2048 * 120

// Scratch (static device globals — no runtime allocation)
__device__ __half g_GT[NGENE * BATCH];    // transposed features, fp16, 16.8 MB
__device__ int2   g_pair[MAX_TOTAL];      // {gene byte offset, weight bits}, 2 MB
__device__ int    g_off[NSETS + 1];       // segment start offsets

// ---------------------------------------------------------------------------
// K0: segment boundary detection (segment_ids sorted, all segments nonempty).
// Fully parallel one-pass; replaces the serial per-warp binary search that
// profiling showed cost 17.2us.
// ---------------------------------------------------------------------------
__global__ void k_offsets(const int* __restrict__ seg, int total) {
    int p = blockIdx.x * blockDim.x + threadIdx.x;
    if (p >= total) return;
    if (p == 0) g_off[0] = 0;
    else {
        int s = seg[p];
        if (seg[p - 1] != s) g_off[s] = p;
    }
    if (p == total - 1) g_off[NSETS] = total;
}

// ---------------------------------------------------------------------------
// K1: warp-per-segment softmax using g_off; emits packed per-edge descriptor
// g_pair[p] = { flat_idx[p] * rowbytes, float_bits(softmax weight) }.
// ---------------------------------------------------------------------------
__global__ void k_softmax(const float* __restrict__ logits,
                          const int* __restrict__ fidx) {
    int warp_id = (blockIdx.x * blockDim.x + threadIdx.x) >> 5;
    if (warp_id >= NSETS) return;
    int lane = threadIdx.x & 31;
    int beg = g_off[warp_id];
    int end = g_off[warp_id + 1];

    float m = -CUDART_INF_F;
    for (int p = beg + lane; p < end; p += 32) m = fmaxf(m, logits[p]);
    #pragma unroll
    for (int o = 16; o; o >>= 1) m = fmaxf(m, __shfl_xor_sync(0xFFFFFFFFu, m, o));

    float sum = 0.0f;
    for (int p = beg + lane; p < end; p += 32) sum += __expf(logits[p] - m);
    #pragma unroll
    for (int o = 16; o; o >>= 1) sum += __shfl_xor_sync(0xFFFFFFFFu, sum, o);

    float inv = (sum > 0.0f) ? (1.0f / sum) : 0.0f;
    for (int p = beg + lane; p < end; p += 32) {
        float w = __expf(logits[p] - m) * inv;
        g_pair[p] = make_int2(fidx[p] * (BATCH * 2), __float_as_int(w));
    }
}

// ---------------------------------------------------------------------------
// K2: tiled transpose + fp16 convert: G(1024 x 8192) f32 -> GT(8192 x 1024) f16
// blockDim (32,8), grid (NGENE/32, BATCH/32)   [round-5 proven form]
// ---------------------------------------------------------------------------
__global__ void k_transpose(const float* __restrict__ G) {
    __shared__ float tile[32][33];
    int gx = blockIdx.x * 32;   // gene base
    int by = blockIdx.y * 32;   // batch base
    int x = gx + threadIdx.x;
    #pragma unroll
    for (int j = 0; j < 32; j += 8)
        tile[threadIdx.y + j][threadIdx.x] = G[(by + threadIdx.y + j) * NGENE + x];
    __syncthreads();
    #pragma unroll
    for (int j = 0; j < 32; j += 8)
        g_GT[(gx + threadIdx.y + j) * BATCH + by + threadIdx.x] =
            __float2half_rn(tile[threadIdx.x][threadIdx.y + j]);
}

// ---------------------------------------------------------------------------
// K3: 2D-tiled aggregation writing out directly (round-9, measured ~28us).
// grid = (NSETS/8, BATCH/256), block = 256 threads.
// Warp w owns set s0+w over batch rows b0..b0+255; thread = 8 rows (uint4).
// Edge descriptors via warp-uniform int2 loads (L1-hot, 1 sector/edge).
// Result tile (8 sets x 256 rows) staged in 8KB smem, then written as
// fully-coalesced 32B chunks: out[b0+t][s0..s0+7].
// ---------------------------------------------------------------------------
__device__ __forceinline__ void fma8(float4& a0, float4& a1, uint4 u, float w) {
    float2 v;
    v = __half22float2(*reinterpret_cast<const __half2*>(&u.x));
    a0.x += w * v.x;  a0.y += w * v.y;
    v = __half22float2(*reinterpret_cast<const __half2*>(&u.y));
    a0.z += w * v.x;  a0.w += w * v.y;
    v = __half22float2(*reinterpret_cast<const __half2*>(&u.z));
    a1.x += w * v.x;  a1.y += w * v.y;
    v = __half22float2(*reinterpret_cast<const __half2*>(&u.w));
    a1.z += w * v.x;  a1.w += w * v.y;
}

__global__ __launch_bounds__(256) void k_agg(float* __restrict__ out) {
    int t    = threadIdx.x;
    int warp = t >> 5;
    int lane = t & 31;
    int s0   = blockIdx.x * 8;
    int b0   = blockIdx.y * 256;
    int s    = s0 + warp;

    int beg = g_off[s];
    int n   = g_off[s + 1] - beg;
    if (n > 128) n = 128;             // structural: n <= 120

    const char* gt = reinterpret_cast<const char*>(g_GT) + b0 * 2 + lane * 16;
    const int2* pr = g_pair + beg;

    float4 a0 = make_float4(0.f, 0.f, 0.f, 0.f);
    float4 a1 = make_float4(0.f, 0.f, 0.f, 0.f);

    int i = 0;
    for (; i + 4 <= n; i += 4) {
        int2 p0 = pr[i + 0];
        int2 p1 = pr[i + 1];
        int2 p2 = pr[i + 2];
        int2 p3 = pr[i + 3];
        uint4 u0 = *reinterpret_cast<const uint4*>(gt + p0.x);
        uint4 u1 = *reinterpret_cast<const uint4*>(gt + p1.x);
        uint4 u2 = *reinterpret_cast<const uint4*>(gt + p2.x);
        uint4 u3 = *reinterpret_cast<const uint4*>(gt + p3.x);
        fma8(a0, a1, u0, __int_as_float(p0.y));
        fma8(a0, a1, u1, __int_as_float(p1.y));
        fma8(a0, a1, u2, __int_as_float(p2.y));
        fma8(a0, a1, u3, __int_as_float(p3.y));
    }
    for (; i < n; i++) {
        int2 p = pr[i];
        uint4 u = *reinterpret_cast<const uint4*>(gt + p.x);
        fma8(a0, a1, u, __int_as_float(p.y));
    }

    // Stage tile: buf[set][local batch row]; thread's rows are 8*lane..8*lane+7
    __shared__ float buf[8][256];
    *reinterpret_cast<float4*>(&buf[warp][lane * 8 + 0]) = a0;
    *reinterpret_cast<float4*>(&buf[warp][lane * 8 + 4]) = a1;
    __syncthreads();

    // Coalesced output: thread t writes out[b0+t][s0..s0+7] (32B, sector-full)
    float4 o0, o1;
    o0.x = buf[0][t]; o0.y = buf[1][t]; o0.z = buf[2][t]; o0.w = buf[3][t];
    o1.x = buf[4][t]; o1.y = buf[5][t]; o1.z = buf[6][t]; o1.w = buf[7][t];
    float* dst = out + (size_t)(b0 + t) * NSETS + s0;
    *reinterpret_cast<float4*>(dst)     = o0;
    *reinterpret_cast<float4*>(dst + 4) = o1;
}

// ---------------------------------------------------------------------------
// Launcher (graph-capturable: kernel launches only, default stream ordering)
// ---------------------------------------------------------------------------
extern "C" void kernel_launch(void* const* d_in, const int* in_sizes, int n_in,
                              void* d_out, int out_size) {
    const float* G      = (const float*)d_in[0];
    const float* logits = (const float*)d_in[1];
    const int*   fidx   = (const int*)d_in[2];
    const int*   seg    = (const int*)d_in[3];
    float*       out    = (float*)d_out;
    int total = in_sizes[1];

    k_offsets<<<(total + 255) / 256, 256>>>(seg, total);
    k_softmax<<<(NSETS * 32 + 255) / 256, 256>>>(logits, fidx);
    k_transpose<<<dim3(NGENE / 32, BATCH / 32), dim3(32, 8)>>>(G);
    k_agg<<<dim3(NSETS / 8, BATCH / 256), 256>>>(out);
}

// round 11
// speedup vs baseline: 1.0887x; 1.0041x over previous
#include <cuda_runtime.h>
#include <cuda_fp16.h>
#include <math_constants.h>

#define BATCH 1024
#define NGENE 8192
#define NSETS 2048
#define MAX_TOTAL 262144   // >= 2048 * 120

// Scratch (static device globals — no runtime allocation)
__device__ __half g_GT[NGENE * BATCH];    // transposed features, fp16, 16.8 MB
__device__ int2   g_pair[MAX_TOTAL];      // {gene byte offset, weight bits}, 2 MB
__device__ int    g_off[NSETS + 1];       // segment start offsets

// ---------------------------------------------------------------------------
// K0: segment boundary detection (segment_ids sorted, all segments nonempty).
// ---------------------------------------------------------------------------
__global__ void k_offsets(const int* __restrict__ seg, int total) {
    int p = blockIdx.x * blockDim.x + threadIdx.x;
    if (p >= total) return;
    if (p == 0) g_off[0] = 0;
    else {
        int s = seg[p];
        if (seg[p - 1] != s) g_off[s] = p;
    }
    if (p == total - 1) g_off[NSETS] = total;
}

// ---------------------------------------------------------------------------
// K1: warp-per-segment softmax using g_off; emits packed per-edge descriptor
// g_pair[p] = { flat_idx[p] * rowbytes, float_bits(softmax weight) }.
// ---------------------------------------------------------------------------
__global__ void k_softmax(const float* __restrict__ logits,
                          const int* __restrict__ fidx) {
    int warp_id = (blockIdx.x * blockDim.x + threadIdx.x) >> 5;
    if (warp_id >= NSETS) return;
    int lane = threadIdx.x & 31;
    int beg = g_off[warp_id];
    int end = g_off[warp_id + 1];

    float m = -CUDART_INF_F;
    for (int p = beg + lane; p < end; p += 32) m = fmaxf(m, logits[p]);
    #pragma unroll
    for (int o = 16; o; o >>= 1) m = fmaxf(m, __shfl_xor_sync(0xFFFFFFFFu, m, o));

    float sum = 0.0f;
    for (int p = beg + lane; p < end; p += 32) sum += __expf(logits[p] - m);
    #pragma unroll
    for (int o = 16; o; o >>= 1) sum += __shfl_xor_sync(0xFFFFFFFFu, sum, o);

    float inv = (sum > 0.0f) ? (1.0f / sum) : 0.0f;
    for (int p = beg + lane; p < end; p += 32) {
        float w = __expf(logits[p] - m) * inv;
        g_pair[p] = make_int2(fidx[p] * (BATCH * 2), __float_as_int(w));
    }
}

// ---------------------------------------------------------------------------
// K2: tiled transpose + fp16 convert: G(1024 x 8192) f32 -> GT(8192 x 1024) f16
// blockDim (32,8), grid (NGENE/32, BATCH/32)
// ---------------------------------------------------------------------------
__global__ void k_transpose(const float* __restrict__ G) {
    __shared__ float tile[32][33];
    int gx = blockIdx.x * 32;   // gene base
    int by = blockIdx.y * 32;   // batch base
    int x = gx + threadIdx.x;
    #pragma unroll
    for (int j = 0; j < 32; j += 8)
        tile[threadIdx.y + j][threadIdx.x] = G[(by + threadIdx.y + j) * NGENE + x];
    __syncthreads();
    #pragma unroll
    for (int j = 0; j < 32; j += 8)
        g_GT[(gx + threadIdx.y + j) * BATCH + by + threadIdx.x] =
            __float2half_rn(tile[threadIdx.x][threadIdx.y + j]);
}

// ---------------------------------------------------------------------------
// K3: 2D-tiled aggregation writing out directly, 8-wide MLP.
// grid = (NSETS/8, BATCH/256), block = 256 threads.
// Warp w owns set s0+w over batch rows b0..b0+255; thread = 8 rows (uint4).
// Main loop: 8 descriptors, then 8 unconditional LDG.128 back-to-back,
// then 8 FMA groups -> 8 independent gathers in flight per thread.
// Result tile (8 sets x 256 rows) staged in 8KB smem, then written as
// fully-coalesced 32B chunks: out[b0+t][s0..s0+7].
// ---------------------------------------------------------------------------
__device__ __forceinline__ void fma8(float4& a0, float4& a1, uint4 u, float w) {
    float2 v;
    v = __half22float2(*reinterpret_cast<const __half2*>(&u.x));
    a0.x += w * v.x;  a0.y += w * v.y;
    v = __half22float2(*reinterpret_cast<const __half2*>(&u.y));
    a0.z += w * v.x;  a0.w += w * v.y;
    v = __half22float2(*reinterpret_cast<const __half2*>(&u.z));
    a1.x += w * v.x;  a1.y += w * v.y;
    v = __half22float2(*reinterpret_cast<const __half2*>(&u.w));
    a1.z += w * v.x;  a1.w += w * v.y;
}

__global__ __launch_bounds__(256) void k_agg(float* __restrict__ out) {
    int t    = threadIdx.x;
    int warp = t >> 5;
    int lane = t & 31;
    int s0   = blockIdx.x * 8;
    int b0   = blockIdx.y * 256;
    int s    = s0 + warp;

    int beg = g_off[s];
    int n   = g_off[s + 1] - beg;
    if (n > 128) n = 128;             // structural: n <= 120

    const char* gt = reinterpret_cast<const char*>(g_GT) + b0 * 2 + lane * 16;
    const int2* pr = g_pair + beg;

    float4 a0 = make_float4(0.f, 0.f, 0.f, 0.f);
    float4 a1 = make_float4(0.f, 0.f, 0.f, 0.f);

    int i = 0;
    for (; i + 8 <= n; i += 8) {
        int2 p[8];
        #pragma unroll
        for (int k = 0; k < 8; k++) p[k] = pr[i + k];
        uint4 u[8];
        #pragma unroll
        for (int k = 0; k < 8; k++)
            u[k] = *reinterpret_cast<const uint4*>(gt + p[k].x);
        #pragma unroll
        for (int k = 0; k < 8; k++)
            fma8(a0, a1, u[k], __int_as_float(p[k].y));
    }
    for (; i < n; i++) {
        int2 p = pr[i];
        uint4 u = *reinterpret_cast<const uint4*>(gt + p.x);
        fma8(a0, a1, u, __int_as_float(p.y));
    }

    // Stage tile: buf[set][local batch row]; thread's rows are 8*lane..8*lane+7
    __shared__ float buf[8][256];
    *reinterpret_cast<float4*>(&buf[warp][lane * 8 + 0]) = a0;
    *reinterpret_cast<float4*>(&buf[warp][lane * 8 + 4]) = a1;
    __syncthreads();

    // Coalesced output: thread t writes out[b0+t][s0..s0+7] (32B, sector-full)
    float4 o0, o1;
    o0.x = buf[0][t]; o0.y = buf[1][t]; o0.z = buf[2][t]; o0.w = buf[3][t];
    o1.x = buf[4][t]; o1.y = buf[5][t]; o1.z = buf[6][t]; o1.w = buf[7][t];
    float* dst = out + (size_t)(b0 + t) * NSETS + s0;
    *reinterpret_cast<float4*>(dst)     = o0;
    *reinterpret_cast<float4*>(dst + 4) = o1;
}

// ---------------------------------------------------------------------------
// Launcher (graph-capturable: kernel launches only, default stream ordering)
// ---------------------------------------------------------------------------
extern "C" void kernel_launch(void* const* d_in, const int* in_sizes, int n_in,
                              void* d_out, int out_size) {
    const float* G      = (const float*)d_in[0];
    const float* logits = (const float*)d_in[1];
    const int*   fidx   = (const int*)d_in[2];
    const int*   seg    = (const int*)d_in[3];
    float*       out    = (float*)d_out;
    int total = in_sizes[1];

    k_offsets<<<(total + 255) / 256, 256>>>(seg, total);
    k_softmax<<<(NSETS * 32 + 255) / 256, 256>>>(logits, fidx);
    k_transpose<<<dim3(NGENE / 32, BATCH / 32), dim3(32, 8)>>>(G);
    k_agg<<<dim3(NSETS / 8, BATCH / 256), 256>>>(out);
}